// round 5
// baseline (speedup 1.0000x reference)
#include <cuda_runtime.h>
#include <math.h>
#include <stdint.h>

// Problem constants
#define TT 512
#define NB 64
#define DD 1024
#define HH 1024
#define TH 3072   // 3*H

// Scratch for gi = x @ w_ih^T + b_ih : [T*N, 3H] fp32 = 402 MB
__device__ float g_gi[TT * NB * TH];

// ---------------------------------------------------------------------------
// Kernel 1: gi GEMM.  C[M=32768, N=3072] = A[M,1024] @ B[3072,1024]^T + bias
// (unchanged from R3 — known good)
// ---------------------------------------------------------------------------
__global__ __launch_bounds__(256) void gi_gemm_kernel(
    const float* __restrict__ A,
    const float* __restrict__ B,
    const float* __restrict__ bias,
    float* __restrict__ C)
{
    __shared__ float As[16][132];
    __shared__ float Bs[16][132];

    const int tid = threadIdx.x;
    const int m0 = blockIdx.y * 128;
    const int n0 = blockIdx.x * 128;
    const int tx = tid & 15;
    const int ty = tid >> 4;
    const int lRow = tid >> 2;
    const int lK   = (tid & 3) * 4;

    float acc[8][8];
#pragma unroll
    for (int i = 0; i < 8; i++)
#pragma unroll
        for (int j = 0; j < 8; j++) acc[i][j] = 0.f;

    for (int k0 = 0; k0 < DD; k0 += 16) {
#pragma unroll
        for (int r = 0; r < 2; r++) {
            int mm = lRow + r * 64;
            float4 va = *(const float4*)&A[(size_t)(m0 + mm) * DD + k0 + lK];
            As[lK + 0][mm] = va.x; As[lK + 1][mm] = va.y;
            As[lK + 2][mm] = va.z; As[lK + 3][mm] = va.w;
            float4 vb = *(const float4*)&B[(size_t)(n0 + mm) * DD + k0 + lK];
            Bs[lK + 0][mm] = vb.x; Bs[lK + 1][mm] = vb.y;
            Bs[lK + 2][mm] = vb.z; Bs[lK + 3][mm] = vb.w;
        }
        __syncthreads();
#pragma unroll
        for (int k = 0; k < 16; k++) {
            float a[8], b[8];
            *(float4*)&a[0] = *(float4*)&As[k][ty * 4];
            *(float4*)&a[4] = *(float4*)&As[k][64 + ty * 4];
            *(float4*)&b[0] = *(float4*)&Bs[k][tx * 4];
            *(float4*)&b[4] = *(float4*)&Bs[k][64 + tx * 4];
#pragma unroll
            for (int i = 0; i < 8; i++)
#pragma unroll
                for (int j = 0; j < 8; j++)
                    acc[i][j] += a[i] * b[j];
        }
        __syncthreads();
    }

#pragma unroll
    for (int i = 0; i < 8; i++) {
        int m = m0 + ((i < 4) ? (ty * 4 + i) : (64 + ty * 4 + i - 4));
#pragma unroll
        for (int j = 0; j < 8; j++) {
            int n = n0 + ((j < 4) ? (tx * 4 + j) : (64 + tx * 4 + j - 4));
            C[(size_t)m * TH + n] = acc[i][j] + bias[n];
        }
    }
}

// ---------------------------------------------------------------------------
// Kernel 2: GRU step — f32x2 packed FMA + double-buffered pipeline.
// 256 threads = 2 K-groups x 128. grid = (64 j-tiles, 2 n-halves).
// Thread: 4 n (as 2 f32x2 pairs) x 1 j x 3 gates = 6 packed accumulators.
// W stored in smem pre-duplicated (w,w) so LDS.64 yields packed operand.
// One barrier per 32-k chunk; LDG of next chunk overlaps compute.
// ---------------------------------------------------------------------------
#define CK 32
#define NCH 16          // 512 / 32 per K-group
#define HS_STRIDE 40    // 32 n + pad, float4/u64 aligned
#define WD_STRIDE 96    // 48 cols duplicated

#define RED_U64 (2 * 128 * 6)
#define HS_FL   (2 * 2 * CK * HS_STRIDE)
#define WD_FL   (2 * 2 * CK * WD_STRIDE)
#define STEP_SMEM_BYTES (RED_U64 * 8 + HS_FL * 4 + WD_FL * 4 + 32 * 4)

#define FMA2(d, a, b, c) \
    asm("fma.rn.f32x2 %0, %1, %2, %3;" : "=l"(d) : "l"(a), "l"(b), "l"(c))

__device__ __forceinline__ float sigmoidf_(float x) {
    return 1.f / (1.f + expf(-x));
}
__device__ __forceinline__ float f2lo(uint64_t v) {
    return __uint_as_float((uint32_t)v);
}
__device__ __forceinline__ float f2hi(uint64_t v) {
    return __uint_as_float((uint32_t)(v >> 32));
}

__global__ __launch_bounds__(256) void gru_step_kernel(
    const float* __restrict__ gi_t,   // [64, 3072]
    const float* __restrict__ mask_t, // [64]
    const float* __restrict__ w_hh,   // [3072, 1024]
    const float* __restrict__ b_hh,   // [3072]
    const float* __restrict__ h_prev, // [64, 1024]
    float* __restrict__ h_out)        // [64, 1024]
{
    extern __shared__ __align__(16) unsigned char smraw[];
    uint64_t* red = (uint64_t*)smraw;                 // [2][128][6]
    float* Hs  = (float*)(smraw + RED_U64 * 8);       // [2 kg][2 buf][CK][HS_STRIDE]
    float* Wd  = Hs + HS_FL;                          // [2 kg][2 buf][CK][WD_STRIDE]
    float* msk = Wd + WD_FL;                          // [32]

    const int tid = threadIdx.x;
    const int kg  = tid >> 7;        // 0/1 K-half
    const int t   = tid & 127;
    const int tn  = t >> 4;          // 0..7
    const int tj  = t & 15;
    const int j0  = blockIdx.x * 16;
    const int n_base = blockIdx.y * 32;
    const int kbase0 = kg * 512;

    float* HsK = Hs + kg * (2 * CK * HS_STRIDE);
    float* WdK = Wd + kg * (2 * CK * WD_STRIDE);

    if (tid < 32) msk[tid] = mask_t[n_base + tid];

    // --- staging address precompute ---
    // H: 2 reps cover 32n x 32k (256 float4 / 128 threads)
    int nh0 = t >> 3,            kqh0 = (t & 7) * 4;
    int nh1 = (t + 128) >> 3,    kqh1 = ((t + 128) & 7) * 4;
    const float* ph0 = h_prev + (n_base + nh0) * HH + kbase0 + kqh0;
    const float* ph1 = h_prev + (n_base + nh1) * HH + kbase0 + kqh1;
    // W: 3 reps cover 48 cols x 32k
    int wc0 = t >> 3,            wkq0 = (t & 7) * 4;
    int wc1 = (t + 128) >> 3,    wkq1 = ((t + 128) & 7) * 4;
    int wc2 = (t + 256) >> 3,    wkq2 = ((t + 256) & 7) * 4;
    const float* pw0 = w_hh + (size_t)((wc0 >> 4) * HH + j0 + (wc0 & 15)) * HH + kbase0 + wkq0;
    const float* pw1 = w_hh + (size_t)((wc1 >> 4) * HH + j0 + (wc1 & 15)) * HH + kbase0 + wkq1;
    const float* pw2 = w_hh + (size_t)((wc2 >> 4) * HH + j0 + (wc2 & 15)) * HH + kbase0 + wkq2;
    const int woff0 = (wc0 >> 4) * 32 + (wc0 & 15) * 2;
    const int woff1 = (wc1 >> 4) * 32 + (wc1 & 15) * 2;
    const int woff2 = (wc2 >> 4) * 32 + (wc2 & 15) * 2;

    uint64_t ar0 = 0, ar1 = 0, az0 = 0, az1 = 0, an0 = 0, an1 = 0;

    float4 h0, h1, w0, w1, w2;

    // prologue: load chunk 0
    h0 = *(const float4*)(ph0);
    h1 = *(const float4*)(ph1);
    w0 = *(const float4*)(pw0);
    w1 = *(const float4*)(pw1);
    w2 = *(const float4*)(pw2);

    __syncthreads();   // msk visible

    // store chunk 0 into buffer 0
    {
        float* Hb = HsK;
        float m0v = msk[nh0], m1v = msk[nh1];
        Hb[(kqh0 + 0) * HS_STRIDE + nh0] = h0.x * m0v;
        Hb[(kqh0 + 1) * HS_STRIDE + nh0] = h0.y * m0v;
        Hb[(kqh0 + 2) * HS_STRIDE + nh0] = h0.z * m0v;
        Hb[(kqh0 + 3) * HS_STRIDE + nh0] = h0.w * m0v;
        Hb[(kqh1 + 0) * HS_STRIDE + nh1] = h1.x * m1v;
        Hb[(kqh1 + 1) * HS_STRIDE + nh1] = h1.y * m1v;
        Hb[(kqh1 + 2) * HS_STRIDE + nh1] = h1.z * m1v;
        Hb[(kqh1 + 3) * HS_STRIDE + nh1] = h1.w * m1v;
        float* Wb = WdK;
        *(float2*)&Wb[(wkq0 + 0) * WD_STRIDE + woff0] = make_float2(w0.x, w0.x);
        *(float2*)&Wb[(wkq0 + 1) * WD_STRIDE + woff0] = make_float2(w0.y, w0.y);
        *(float2*)&Wb[(wkq0 + 2) * WD_STRIDE + woff0] = make_float2(w0.z, w0.z);
        *(float2*)&Wb[(wkq0 + 3) * WD_STRIDE + woff0] = make_float2(w0.w, w0.w);
        *(float2*)&Wb[(wkq1 + 0) * WD_STRIDE + woff1] = make_float2(w1.x, w1.x);
        *(float2*)&Wb[(wkq1 + 1) * WD_STRIDE + woff1] = make_float2(w1.y, w1.y);
        *(float2*)&Wb[(wkq1 + 2) * WD_STRIDE + woff1] = make_float2(w1.z, w1.z);
        *(float2*)&Wb[(wkq1 + 3) * WD_STRIDE + woff1] = make_float2(w1.w, w1.w);
        *(float2*)&Wb[(wkq2 + 0) * WD_STRIDE + woff2] = make_float2(w2.x, w2.x);
        *(float2*)&Wb[(wkq2 + 1) * WD_STRIDE + woff2] = make_float2(w2.y, w2.y);
        *(float2*)&Wb[(wkq2 + 2) * WD_STRIDE + woff2] = make_float2(w2.z, w2.z);
        *(float2*)&Wb[(wkq2 + 3) * WD_STRIDE + woff2] = make_float2(w2.w, w2.w);
    }
    __syncthreads();

    for (int c = 0; c < NCH; c++) {
        // issue LDG for next chunk (overlaps with compute below)
        if (c + 1 < NCH) {
            int kc = (c + 1) * CK;
            h0 = *(const float4*)(ph0 + kc);
            h1 = *(const float4*)(ph1 + kc);
            w0 = *(const float4*)(pw0 + kc);
            w1 = *(const float4*)(pw1 + kc);
            w2 = *(const float4*)(pw2 + kc);
        }

        // compute current chunk from buffer c&1
        {
            const float* Hb = HsK + (c & 1) * (CK * HS_STRIDE);
            const float* Wb = WdK + (c & 1) * (CK * WD_STRIDE);
#pragma unroll
            for (int k = 0; k < CK; k++) {
                const float* hrow = Hb + k * HS_STRIDE + tn * 4;
                uint64_t h01 = *(const uint64_t*)(hrow);
                uint64_t h23 = *(const uint64_t*)(hrow + 2);
                const float* wrow = Wb + k * WD_STRIDE + 2 * tj;
                uint64_t wr = *(const uint64_t*)(wrow);
                uint64_t wz = *(const uint64_t*)(wrow + 32);
                uint64_t wn = *(const uint64_t*)(wrow + 64);
                FMA2(ar0, h01, wr, ar0);
                FMA2(ar1, h23, wr, ar1);
                FMA2(az0, h01, wz, az0);
                FMA2(az1, h23, wz, az1);
                FMA2(an0, h01, wn, an0);
                FMA2(an1, h23, wn, an1);
            }
        }

        // store next chunk into the other buffer, then barrier
        if (c + 1 < NCH) {
            float* Hb = HsK + ((c + 1) & 1) * (CK * HS_STRIDE);
            float m0v = msk[nh0], m1v = msk[nh1];
            Hb[(kqh0 + 0) * HS_STRIDE + nh0] = h0.x * m0v;
            Hb[(kqh0 + 1) * HS_STRIDE + nh0] = h0.y * m0v;
            Hb[(kqh0 + 2) * HS_STRIDE + nh0] = h0.z * m0v;
            Hb[(kqh0 + 3) * HS_STRIDE + nh0] = h0.w * m0v;
            Hb[(kqh1 + 0) * HS_STRIDE + nh1] = h1.x * m1v;
            Hb[(kqh1 + 1) * HS_STRIDE + nh1] = h1.y * m1v;
            Hb[(kqh1 + 2) * HS_STRIDE + nh1] = h1.z * m1v;
            Hb[(kqh1 + 3) * HS_STRIDE + nh1] = h1.w * m1v;
            float* Wb = WdK + ((c + 1) & 1) * (CK * WD_STRIDE);
            *(float2*)&Wb[(wkq0 + 0) * WD_STRIDE + woff0] = make_float2(w0.x, w0.x);
            *(float2*)&Wb[(wkq0 + 1) * WD_STRIDE + woff0] = make_float2(w0.y, w0.y);
            *(float2*)&Wb[(wkq0 + 2) * WD_STRIDE + woff0] = make_float2(w0.z, w0.z);
            *(float2*)&Wb[(wkq0 + 3) * WD_STRIDE + woff0] = make_float2(w0.w, w0.w);
            *(float2*)&Wb[(wkq1 + 0) * WD_STRIDE + woff1] = make_float2(w1.x, w1.x);
            *(float2*)&Wb[(wkq1 + 1) * WD_STRIDE + woff1] = make_float2(w1.y, w1.y);
            *(float2*)&Wb[(wkq1 + 2) * WD_STRIDE + woff1] = make_float2(w1.z, w1.z);
            *(float2*)&Wb[(wkq1 + 3) * WD_STRIDE + woff1] = make_float2(w1.w, w1.w);
            *(float2*)&Wb[(wkq2 + 0) * WD_STRIDE + woff2] = make_float2(w2.x, w2.x);
            *(float2*)&Wb[(wkq2 + 1) * WD_STRIDE + woff2] = make_float2(w2.y, w2.y);
            *(float2*)&Wb[(wkq2 + 2) * WD_STRIDE + woff2] = make_float2(w2.z, w2.z);
            *(float2*)&Wb[(wkq2 + 3) * WD_STRIDE + woff2] = make_float2(w2.w, w2.w);
            __syncthreads();
        }
    }

    // publish partials
    {
        uint64_t* my = red + ((size_t)(kg << 7) + t) * 6;
        my[0] = ar0; my[1] = ar1;
        my[2] = az0; my[3] = az1;
        my[4] = an0; my[5] = an1;
    }
    __syncthreads();

    // tail: every thread produces 2 outputs.
    // kg selects the f32x2 pair: kg0 -> n offsets {0,1}, kg1 -> {2,3}
    {
        const uint64_t* p0 = red + (size_t)t * 6;
        const uint64_t* p1 = red + (size_t)(128 + t) * 6;
        const int pi = kg;
        uint64_t pr = 0, pz = 0, pn = 0;
        uint64_t vr0 = p0[pi],     vr1 = p1[pi];
        uint64_t vz0 = p0[2 + pi], vz1 = p1[2 + pi];
        uint64_t vn0 = p0[4 + pi], vn1 = p1[4 + pi];
        (void)pr; (void)pz; (void)pn;

        const int j = j0 + tj;
        const float br = b_hh[j];
        const float bz = b_hh[HH + j];
        const float bn = b_hh[2 * HH + j];

#pragma unroll
        for (int h2 = 0; h2 < 2; h2++) {
            int nl = tn * 4 + pi * 2 + h2;
            int nglob = n_base + nl;
            float ghr = (h2 ? f2hi(vr0) + f2hi(vr1) : f2lo(vr0) + f2lo(vr1)) + br;
            float ghz = (h2 ? f2hi(vz0) + f2hi(vz1) : f2lo(vz0) + f2lo(vz1)) + bz;
            float ghn = (h2 ? f2hi(vn0) + f2hi(vn1) : f2lo(vn0) + f2lo(vn1)) + bn;
            const float* girow = gi_t + (size_t)nglob * TH;
            float gir = girow[j];
            float giz = girow[HH + j];
            float gin = girow[2 * HH + j];
            float hm  = h_prev[nglob * HH + j] * msk[nl];
            float r  = sigmoidf_(gir + ghr);
            float z  = sigmoidf_(giz + ghz);
            float nn = tanhf(gin + r * ghn);
            h_out[nglob * HH + j] = (1.f - z) * nn + z * hm;
        }
    }
}

// ---------------------------------------------------------------------------
extern "C" void kernel_launch(void* const* d_in, const int* in_sizes, int n_in,
                              void* d_out, int out_size)
{
    const float* x    = (const float*)d_in[0];
    const float* hx   = (const float*)d_in[1];
    const float* mask = (const float*)d_in[2];
    const float* w_ih = (const float*)d_in[3];
    const float* w_hh = (const float*)d_in[4];
    const float* b_ih = (const float*)d_in[5];
    const float* b_hh = (const float*)d_in[6];
    float* out = (float*)d_out;

    float* gi = nullptr;
    cudaGetSymbolAddress((void**)&gi, g_gi);

    cudaFuncSetAttribute(gru_step_kernel,
                         cudaFuncAttributeMaxDynamicSharedMemorySize,
                         STEP_SMEM_BYTES);

    // Phase 1: bulk input projection
    dim3 gg(TH / 128, (TT * NB) / 128);   // (24, 256)
    gi_gemm_kernel<<<gg, 256>>>(x, w_ih, b_ih, gi);

    // Phase 2: sequential scan
    dim3 sg(HH / 16, 2);                  // 128 blocks
    for (int tm = 0; tm < TT; tm++) {
        const float* hp = (tm == 0) ? hx : (out + (size_t)(tm - 1) * NB * HH);
        gru_step_kernel<<<sg, 256, STEP_SMEM_BYTES>>>(
            gi + (size_t)tm * NB * TH,
            mask + tm * NB,
            w_hh, b_hh,
            hp,
            out + (size_t)tm * NB * HH);
    }

    // h_final == out[T-1]
    cudaMemcpyAsync(out + (size_t)TT * NB * HH,
                    out + (size_t)(TT - 1) * NB * HH,
                    (size_t)NB * HH * sizeof(float),
                    cudaMemcpyDeviceToDevice, 0);
}